// round 2
// baseline (speedup 1.0000x reference)
#include <cuda_runtime.h>
#include <math.h>

#define NTRAJ 512
#define NTP 64
#define NSTEP 63
#define NIN 512
#define NLAT 1024
#define NUNITS 100
#define NCLUS 256
#define DCAT 1536

// ---------------- scratch (device globals: no runtime allocation) ----------
__device__ float g_h[NTRAJ * NLAT];           // recurrent state
__device__ float g_u[NTRAJ * NLAT];           // update gate
__device__ float g_hr[NTRAJ * NLAT];          // h * r
__device__ float g_t1p[8 * NTRAJ * NUNITS];   // K-split partials of h@W1
__device__ float g_t1[NTRAJ * NUNITS];        // tanh(h@W1+b1)
__device__ float g_lp[4 * NTRAJ * NCLUS];     // K-split partials of h@We

enum { ASRC_PLAIN = 0, ASRC_CONCAT = 1 };
enum { EPI_GATES = 0, EPI_NEWH = 1, EPI_EULER = 2, EPI_LOGITS = 3 };

#define BM 64
#define BN 64
#define BK 16

#define FFMA2(c, a, b) asm("fma.rn.f32x2 %0, %1, %2, %0;" : "+l"(c) : "l"(a), "l"(b))

// Generic 64x64 tiled fp32 GEMM, 128 threads, 8x4 outputs per thread.
// Inner product uses packed fma.rn.f32x2 (2 FMA/instr, full-rate on B300).
template <int ASRC, int EPI>
__global__ void __launch_bounds__(128) gemm_k(
    const float* __restrict__ A, const float* __restrict__ Ad, int lda,
    const float* __restrict__ B0, const float* __restrict__ B1, int ldb,
    int K, int KS,
    const float* __restrict__ bias0, const float* __restrict__ bias1,
    const float* __restrict__ ts, const float* __restrict__ uin,
    float* __restrict__ hbuf, float* __restrict__ out0, float* __restrict__ out1,
    int t)
{
    __shared__ __align__(16) float As[BK][68];   // 68: 16B-aligned rows, conflict-free
    __shared__ __align__(16) float Bs[BK][BN];

    const int tid = threadIdx.x;
    const int tx = tid & 15;       // 16 col groups * 4 cols
    const int ty = tid >> 4;       // 8 row groups * 8 rows
    const int r0 = blockIdx.x * BM;
    const int c0 = blockIdx.y * BN;

    const float* Bp = B0;
    int cb = c0;
    if (EPI == EPI_GATES) {                 // N=2048: left half = W_u, right = W_r
        if (c0 >= NLAT) { Bp = B1; cb = c0 - NLAT; }
    }

    // accumulators: 4 row-pairs x 4 cols, packed f32x2
    unsigned long long accp[4][4];
#pragma unroll
    for (int i = 0; i < 4; i++)
#pragma unroll
        for (int j = 0; j < 4; j++) accp[i][j] = 0ull;

    const int k0 = blockIdx.z * KS;
    const int k1 = (k0 + KS < K) ? (k0 + KS) : K;

    for (int kk = k0; kk < k1; kk += BK) {
        // ---- load A tile (transposed into shared) ----
#pragma unroll
        for (int i = 0; i < 8; i++) {
            int idx = tid + i * 128;
            int m = idx >> 4, kq = idx & 15;
            int gk = kk + kq;
            float v = 0.f;
            if (ASRC == ASRC_PLAIN) {
                if (gk < k1) v = A[(r0 + m) * lda + gk];
            } else { // ASRC_CONCAT: A = [state(512x1024) | data[:, t, :](512x512)]
                if (gk < NLAT) v = A[(r0 + m) * NLAT + gk];
                else           v = Ad[(r0 + m) * (NTP * NIN) + t * NIN + (gk - NLAT)];
            }
            As[kq][m] = v;
        }
        // ---- load B tile ----
#pragma unroll
        for (int i = 0; i < 8; i++) {
            int idx = tid + i * 128;
            int kq = idx >> 6, n = idx & 63;
            int gk = kk + kq;
            Bs[kq][n] = (gk < k1) ? Bp[gk * ldb + cb + n] : 0.f;
        }
        __syncthreads();
        // ---- packed FMA ----
#pragma unroll
        for (int k = 0; k < BK; k++) {
            const unsigned long long* Ap =
                (const unsigned long long*)&As[k][ty * 8];
            unsigned long long ap0 = Ap[0], ap1 = Ap[1], ap2 = Ap[2], ap3 = Ap[3];
            float4 b = *(const float4*)&Bs[k][tx * 4];
            unsigned long long bd0, bd1, bd2, bd3;
            asm("mov.b64 %0, {%1, %1};" : "=l"(bd0) : "f"(b.x));
            asm("mov.b64 %0, {%1, %1};" : "=l"(bd1) : "f"(b.y));
            asm("mov.b64 %0, {%1, %1};" : "=l"(bd2) : "f"(b.z));
            asm("mov.b64 %0, {%1, %1};" : "=l"(bd3) : "f"(b.w));
            FFMA2(accp[0][0], ap0, bd0); FFMA2(accp[0][1], ap0, bd1);
            FFMA2(accp[0][2], ap0, bd2); FFMA2(accp[0][3], ap0, bd3);
            FFMA2(accp[1][0], ap1, bd0); FFMA2(accp[1][1], ap1, bd1);
            FFMA2(accp[1][2], ap1, bd2); FFMA2(accp[1][3], ap1, bd3);
            FFMA2(accp[2][0], ap2, bd0); FFMA2(accp[2][1], ap2, bd1);
            FFMA2(accp[2][2], ap2, bd2); FFMA2(accp[2][3], ap2, bd3);
            FFMA2(accp[3][0], ap3, bd0); FFMA2(accp[3][1], ap3, bd1);
            FFMA2(accp[3][2], ap3, bd2); FFMA2(accp[3][3], ap3, bd3);
        }
        __syncthreads();
    }

    // ---- epilogue ----
#pragma unroll
    for (int i = 0; i < 8; i++) {
        int row = r0 + ty * 8 + i;
#pragma unroll
        for (int j = 0; j < 4; j++) {
            int col = c0 + tx * 4 + j;
            float2 pr = *(float2*)&accp[i >> 1][j];
            float v = (i & 1) ? pr.y : pr.x;
            if (EPI == EPI_GATES) {
                float b = (col < NLAT) ? bias0[col] : bias1[col - NLAT];
                float s = 1.f / (1.f + expf(-(v + b)));
                if (col < NLAT) {
                    out0[row * NLAT + col] = s;                       // u gate
                } else {
                    int c = col - NLAT;
                    out1[row * NLAT + c] = hbuf[row * NLAT + c] * s;  // h*r
                }
            } else if (EPI == EPI_NEWH) {
                float n  = v + bias0[col];
                float uu = uin[row * NLAT + col];
                float ho = hbuf[row * NLAT + col];
                hbuf[row * NLAT + col] = (1.f - uu) * n + uu * ho;    // GRU blend
            } else if (EPI == EPI_EULER) {
                float sub = 0.5f * (ts[t + 1] - ts[t]);               // dt / (N_INTER-1)
                hbuf[row * NLAT + col] += sub * (v + bias0[col]);
            } else { // EPI_LOGITS: write K-split partial (bias added in softmax)
                out0[blockIdx.z * (NTRAJ * NCLUS) + row * NCLUS + col] = v;
            }
        }
    }
}

// h@W1 partial GEMM: grid (64 row-blocks of 8, 8 K-splits of 128). N=100.
__global__ void __launch_bounds__(256) ode1_k(const float* __restrict__ h,
                                              const float* __restrict__ W1,
                                              float* __restrict__ t1p)
{
    __shared__ float As[16][9];     // padded: conflict-free stores
    __shared__ float Ws[16][128];
    const int tid = threadIdx.x;
    const int tx = tid & 127;       // col (active < 100)
    const int ty = tid >> 7;        // 0..1, 4 rows each
    const int r0 = blockIdx.x * 8;
    const int ks = blockIdx.y;
    float acc[4] = {0.f, 0.f, 0.f, 0.f};

    for (int kk = ks * 128; kk < ks * 128 + 128; kk += 16) {
        if (tid < 128) {
            int m = tid >> 4, kq = tid & 15;
            As[kq][m] = h[(r0 + m) * NLAT + kk + kq];
        }
#pragma unroll
        for (int j = 0; j < 8; j++) {
            int kq = ty * 8 + j;
            Ws[kq][tx] = (tx < NUNITS) ? W1[(kk + kq) * NUNITS + tx] : 0.f;
        }
        __syncthreads();
        if (tx < NUNITS) {
#pragma unroll
            for (int kq = 0; kq < 16; kq++) {
                float w = Ws[kq][tx];
#pragma unroll
                for (int r = 0; r < 4; r++)
                    acc[r] += As[kq][ty * 4 + r] * w;
            }
        }
        __syncthreads();
    }
    if (tx < NUNITS) {
#pragma unroll
        for (int r = 0; r < 4; r++)
            t1p[ks * (NTRAJ * NUNITS) + (r0 + ty * 4 + r) * NUNITS + tx] = acc[r];
    }
}

// t1 = tanh(b1 + sum of 8 K-split partials)
__global__ void __launch_bounds__(256) tanhsum_k(const float* __restrict__ t1p,
                                                 const float* __restrict__ b1,
                                                 float* __restrict__ t1)
{
    int i = blockIdx.x * 256 + threadIdx.x;
    if (i >= NTRAJ * NUNITS) return;
    int col = i % NUNITS;
    float s = b1[col];
#pragma unroll
    for (int p = 0; p < 8; p++) s += t1p[p * (NTRAJ * NUNITS) + i];
    t1[i] = tanhf(s);
}

// Sum logits partials + bias, softmax over 256 clusters, and copy states out.
__global__ void __launch_bounds__(256) softmax_states_k(
    const float* __restrict__ lp, const float* __restrict__ be,
    const float* __restrict__ h,
    float* __restrict__ prob_out, float* __restrict__ state_out)
{
    const int row = blockIdx.x;
    const int tid = threadIdx.x;
    __shared__ float smax[8], ssum[8];

    float v = be[tid];
#pragma unroll
    for (int s = 0; s < 4; s++) v += lp[s * (NTRAJ * NCLUS) + row * NCLUS + tid];

    float m = v;
#pragma unroll
    for (int o = 16; o > 0; o >>= 1) m = fmaxf(m, __shfl_xor_sync(0xffffffffu, m, o));
    if ((tid & 31) == 0) smax[tid >> 5] = m;
    __syncthreads();
    float mx = smax[0];
#pragma unroll
    for (int w = 1; w < 8; w++) mx = fmaxf(mx, smax[w]);

    float e = expf(v - mx);
    float s = e;
#pragma unroll
    for (int o = 16; o > 0; o >>= 1) s += __shfl_xor_sync(0xffffffffu, s, o);
    if ((tid & 31) == 0) ssum[tid >> 5] = s;
    __syncthreads();
    float tot = 0.f;
#pragma unroll
    for (int w = 0; w < 8; w++) tot += ssum[w];

    prob_out[row * NCLUS + tid] = e / tot;
#pragma unroll
    for (int i = 0; i < 4; i++)
        state_out[row * NLAT + i * 256 + tid] = h[row * NLAT + i * 256 + tid];
}

__global__ void zero_k(float* __restrict__ p, int n)
{
    int i = blockIdx.x * blockDim.x + threadIdx.x;
    if (i < n) p[i] = 0.f;
}

extern "C" void kernel_launch(void* const* d_in, const int* in_sizes, int n_in,
                              void* d_out, int out_size)
{
    const float* data = (const float*)d_in[0];
    const float* ts   = (const float*)d_in[1];
    const float* W_u  = (const float*)d_in[2];
    const float* b_u  = (const float*)d_in[3];
    const float* W_r  = (const float*)d_in[4];
    const float* b_r  = (const float*)d_in[5];
    const float* W_n  = (const float*)d_in[6];
    const float* b_n  = (const float*)d_in[7];
    const float* W1   = (const float*)d_in[8];
    const float* b1   = (const float*)d_in[9];
    const float* W2   = (const float*)d_in[10];
    const float* b2   = (const float*)d_in[11];
    const float* We   = (const float*)d_in[12];
    const float* be   = (const float*)d_in[13];
    float* out = (float*)d_out;

    float *h, *u, *hr, *t1p, *t1, *lp;
    cudaGetSymbolAddress((void**)&h, g_h);
    cudaGetSymbolAddress((void**)&u, g_u);
    cudaGetSymbolAddress((void**)&hr, g_hr);
    cudaGetSymbolAddress((void**)&t1p, g_t1p);
    cudaGetSymbolAddress((void**)&t1, g_t1);
    cudaGetSymbolAddress((void**)&lp, g_lp);

    zero_k<<<(NTRAJ * NLAT + 255) / 256, 256>>>(h, NTRAJ * NLAT);

    float* probs  = out;
    float* states = out + (size_t)NSTEP * NTRAJ * NCLUS;

    for (int t = 0; t < NSTEP; t++) {
        // u,r gates: [h|x] @ [W_u | W_r], sigmoid; emits u and h*r
        gemm_k<ASRC_CONCAT, EPI_GATES><<<dim3(8, 32, 1), 128>>>(
            h, data, NLAT, W_u, W_r, NLAT, DCAT, DCAT,
            b_u, b_r, nullptr, nullptr, h, u, hr, t);
        // n gate + GRU blend: h = (1-u)*([h*r|x] @ W_n + b_n) + u*h
        gemm_k<ASRC_CONCAT, EPI_NEWH><<<dim3(8, 16, 1), 128>>>(
            hr, data, NLAT, W_n, nullptr, NLAT, DCAT, DCAT,
            b_n, nullptr, nullptr, u, h, nullptr, nullptr, t);
        // 2 Euler steps: h += sub * (tanh(h@W1+b1) @ W2 + b2)
        for (int e = 0; e < 2; e++) {
            ode1_k<<<dim3(64, 8), 256>>>(h, W1, t1p);
            tanhsum_k<<<(NTRAJ * NUNITS + 255) / 256, 256>>>(t1p, b1, t1);
            gemm_k<ASRC_PLAIN, EPI_EULER><<<dim3(8, 16, 1), 128>>>(
                t1, nullptr, NUNITS, W2, nullptr, NLAT, NUNITS, NUNITS,
                b2, b1, ts, nullptr, h, nullptr, nullptr, t);
        }
        // emission logits (K split by 4 for parallelism), then softmax + state copy
        gemm_k<ASRC_PLAIN, EPI_LOGITS><<<dim3(8, 4, 4), 128>>>(
            h, nullptr, NLAT, We, nullptr, NCLUS, NLAT, 256,
            nullptr, nullptr, nullptr, nullptr, nullptr, lp, nullptr, t);
        softmax_states_k<<<NTRAJ, 256>>>(lp, be, h,
            probs  + (size_t)t * NTRAJ * NCLUS,
            states + (size_t)t * NTRAJ * NLAT);
    }
}

// round 3
// speedup vs baseline: 1.4160x; 1.4160x over previous
#include <cuda_runtime.h>
#include <math.h>

#define NTRAJ 512
#define NTP 64
#define NSTEP 63
#define NIN 512
#define NLAT 1024
#define NUNITS 100
#define NCLUS 256
#define DCAT 1536

// ---------------- scratch (device globals: no runtime allocation) ----------
__device__ float g_h[NTRAJ * NLAT];           // recurrent state
__device__ float g_u[NTRAJ * NLAT];           // update gate
__device__ float g_hr[NTRAJ * NLAT];          // h * r
__device__ float g_t1p[8 * NTRAJ * NUNITS];   // K-split partials of h@W1
__device__ float g_t1[NTRAJ * NUNITS];        // tanh(h@W1+b1)
__device__ float g_lp[4 * NTRAJ * NCLUS];     // K-split partials of h@We

enum { ASRC_PLAIN = 0, ASRC_CONCAT = 1 };
enum { EPI_GATES = 0, EPI_NEWH = 1, EPI_EULER = 2, EPI_LOGITS = 3 };

#define BM 64
#define BN 64
#define BK 16

// Generic 64x64 tiled fp32 GEMM, 128 threads, 8x4 outputs per thread.
// Scalar FFMA inner loop (measured fastest on sm_103a; f32x2 regressed).
template <int ASRC, int EPI>
__global__ void __launch_bounds__(128) gemm_k(
    const float* __restrict__ A, const float* __restrict__ Ad, int lda,
    const float* __restrict__ B0, const float* __restrict__ B1, int ldb,
    int K, int KS,
    const float* __restrict__ bias0, const float* __restrict__ bias1,
    const float* __restrict__ ts, const float* __restrict__ uin,
    float* __restrict__ hbuf, float* __restrict__ out0, float* __restrict__ out1,
    int t)
{
    __shared__ __align__(16) float As[BK][68];   // padded, conflict-free
    __shared__ __align__(16) float Bs[BK][BN];

    const int tid = threadIdx.x;
    const int tx = tid & 15;       // 16 col groups * 4 cols
    const int ty = tid >> 4;       // 8 row groups * 8 rows
    const int r0 = blockIdx.x * BM;
    const int c0 = blockIdx.y * BN;

    const float* Bp = B0;
    int cb = c0;
    if (EPI == EPI_GATES) {                 // N=2048: left half = W_u, right = W_r
        if (c0 >= NLAT) { Bp = B1; cb = c0 - NLAT; }
    }

    float acc[8][4];
#pragma unroll
    for (int i = 0; i < 8; i++)
#pragma unroll
        for (int j = 0; j < 4; j++) acc[i][j] = 0.f;

    const int k0 = blockIdx.z * KS;
    const int k1 = (k0 + KS < K) ? (k0 + KS) : K;

    for (int kk = k0; kk < k1; kk += BK) {
        // ---- load A tile (transposed into shared) ----
#pragma unroll
        for (int i = 0; i < 8; i++) {
            int idx = tid + i * 128;
            int m = idx >> 4, kq = idx & 15;
            int gk = kk + kq;
            float v = 0.f;
            if (ASRC == ASRC_PLAIN) {
                if (gk < k1) v = A[(r0 + m) * lda + gk];
            } else { // ASRC_CONCAT: A = [state(512x1024) | data[:, t, :](512x512)]
                if (gk < NLAT) v = A[(r0 + m) * NLAT + gk];
                else           v = Ad[(r0 + m) * (NTP * NIN) + t * NIN + (gk - NLAT)];
            }
            As[kq][m] = v;
        }
        // ---- load B tile ----
#pragma unroll
        for (int i = 0; i < 8; i++) {
            int idx = tid + i * 128;
            int kq = idx >> 6, n = idx & 63;
            int gk = kk + kq;
            Bs[kq][n] = (gk < k1) ? Bp[gk * ldb + cb + n] : 0.f;
        }
        __syncthreads();
        // ---- scalar FMA ----
#pragma unroll
        for (int k = 0; k < BK; k++) {
            float4 a0 = *(const float4*)&As[k][ty * 8];
            float4 a1 = *(const float4*)&As[k][ty * 8 + 4];
            float4 b  = *(const float4*)&Bs[k][tx * 4];
            float av[8] = {a0.x, a0.y, a0.z, a0.w, a1.x, a1.y, a1.z, a1.w};
            float bv[4] = {b.x, b.y, b.z, b.w};
#pragma unroll
            for (int i = 0; i < 8; i++)
#pragma unroll
                for (int j = 0; j < 4; j++)
                    acc[i][j] += av[i] * bv[j];
        }
        __syncthreads();
    }

    // ---- epilogue ----
#pragma unroll
    for (int i = 0; i < 8; i++) {
        int row = r0 + ty * 8 + i;
#pragma unroll
        for (int j = 0; j < 4; j++) {
            int col = c0 + tx * 4 + j;
            float v = acc[i][j];
            if (EPI == EPI_GATES) {
                float b = (col < NLAT) ? bias0[col] : bias1[col - NLAT];
                float s = 1.f / (1.f + expf(-(v + b)));
                if (col < NLAT) {
                    out0[row * NLAT + col] = s;                       // u gate
                } else {
                    int c = col - NLAT;
                    out1[row * NLAT + c] = hbuf[row * NLAT + c] * s;  // h*r
                }
            } else if (EPI == EPI_NEWH) {
                float n  = v + bias0[col];
                float uu = uin[row * NLAT + col];
                float ho = hbuf[row * NLAT + col];
                hbuf[row * NLAT + col] = (1.f - uu) * n + uu * ho;    // GRU blend
            } else if (EPI == EPI_EULER) {
                float sub = 0.5f * (ts[t + 1] - ts[t]);               // dt / (N_INTER-1)
                hbuf[row * NLAT + col] += sub * (v + bias0[col]);
            } else { // EPI_LOGITS: write K-split partial (bias added in softmax)
                out0[blockIdx.z * (NTRAJ * NCLUS) + row * NCLUS + col] = v;
            }
        }
    }
}

// h@W1 partial GEMM: grid (64 row-blocks of 8, 8 K-splits of 128). N=100.
__global__ void __launch_bounds__(256) ode1_k(const float* __restrict__ h,
                                              const float* __restrict__ W1,
                                              float* __restrict__ t1p)
{
    __shared__ float As[16][9];     // padded: conflict-free stores
    __shared__ float Ws[16][128];
    const int tid = threadIdx.x;
    const int tx = tid & 127;       // col (active < 100)
    const int ty = tid >> 7;        // 0..1, 4 rows each
    const int r0 = blockIdx.x * 8;
    const int ks = blockIdx.y;
    float acc[4] = {0.f, 0.f, 0.f, 0.f};

    for (int kk = ks * 128; kk < ks * 128 + 128; kk += 16) {
        if (tid < 128) {
            int m = tid >> 4, kq = tid & 15;
            As[kq][m] = h[(r0 + m) * NLAT + kk + kq];
        }
#pragma unroll
        for (int j = 0; j < 8; j++) {
            int kq = ty * 8 + j;
            Ws[kq][tx] = (tx < NUNITS) ? W1[(kk + kq) * NUNITS + tx] : 0.f;
        }
        __syncthreads();
        if (tx < NUNITS) {
#pragma unroll
            for (int kq = 0; kq < 16; kq++) {
                float w = Ws[kq][tx];
#pragma unroll
                for (int r = 0; r < 4; r++)
                    acc[r] += As[kq][ty * 4 + r] * w;
            }
        }
        __syncthreads();
    }
    if (tx < NUNITS) {
#pragma unroll
        for (int r = 0; r < 4; r++)
            t1p[ks * (NTRAJ * NUNITS) + (r0 + ty * 4 + r) * NUNITS + tx] = acc[r];
    }
}

// t1 = tanh(b1 + sum of 8 K-split partials)
__global__ void __launch_bounds__(256) tanhsum_k(const float* __restrict__ t1p,
                                                 const float* __restrict__ b1,
                                                 float* __restrict__ t1)
{
    int i = blockIdx.x * 256 + threadIdx.x;
    if (i >= NTRAJ * NUNITS) return;
    int col = i % NUNITS;
    float s = b1[col];
#pragma unroll
    for (int p = 0; p < 8; p++) s += t1p[p * (NTRAJ * NUNITS) + i];
    t1[i] = tanhf(s);
}

// Sum logits partials + bias, softmax over 256 clusters, and copy states out.
__global__ void __launch_bounds__(256) softmax_states_k(
    const float* __restrict__ lp, const float* __restrict__ be,
    const float* __restrict__ h,
    float* __restrict__ prob_out, float* __restrict__ state_out)
{
    const int row = blockIdx.x;
    const int tid = threadIdx.x;
    __shared__ float smax[8], ssum[8];

    float v = be[tid];
#pragma unroll
    for (int s = 0; s < 4; s++) v += lp[s * (NTRAJ * NCLUS) + row * NCLUS + tid];

    float m = v;
#pragma unroll
    for (int o = 16; o > 0; o >>= 1) m = fmaxf(m, __shfl_xor_sync(0xffffffffu, m, o));
    if ((tid & 31) == 0) smax[tid >> 5] = m;
    __syncthreads();
    float mx = smax[0];
#pragma unroll
    for (int w = 1; w < 8; w++) mx = fmaxf(mx, smax[w]);

    float e = expf(v - mx);
    float s = e;
#pragma unroll
    for (int o = 16; o > 0; o >>= 1) s += __shfl_xor_sync(0xffffffffu, s, o);
    if ((tid & 31) == 0) ssum[tid >> 5] = s;
    __syncthreads();
    float tot = 0.f;
#pragma unroll
    for (int w = 0; w < 8; w++) tot += ssum[w];

    prob_out[row * NCLUS + tid] = e / tot;
#pragma unroll
    for (int i = 0; i < 4; i++)
        state_out[row * NLAT + i * 256 + tid] = h[row * NLAT + i * 256 + tid];
}

__global__ void zero_k(float* __restrict__ p, int n)
{
    int i = blockIdx.x * blockDim.x + threadIdx.x;
    if (i < n) p[i] = 0.f;
}

extern "C" void kernel_launch(void* const* d_in, const int* in_sizes, int n_in,
                              void* d_out, int out_size)
{
    const float* data = (const float*)d_in[0];
    const float* ts   = (const float*)d_in[1];
    const float* W_u  = (const float*)d_in[2];
    const float* b_u  = (const float*)d_in[3];
    const float* W_r  = (const float*)d_in[4];
    const float* b_r  = (const float*)d_in[5];
    const float* W_n  = (const float*)d_in[6];
    const float* b_n  = (const float*)d_in[7];
    const float* W1   = (const float*)d_in[8];
    const float* b1   = (const float*)d_in[9];
    const float* W2   = (const float*)d_in[10];
    const float* b2   = (const float*)d_in[11];
    const float* We   = (const float*)d_in[12];
    const float* be   = (const float*)d_in[13];
    float* out = (float*)d_out;

    float *h, *u, *hr, *t1p, *t1, *lp;
    cudaGetSymbolAddress((void**)&h, g_h);
    cudaGetSymbolAddress((void**)&u, g_u);
    cudaGetSymbolAddress((void**)&hr, g_hr);
    cudaGetSymbolAddress((void**)&t1p, g_t1p);
    cudaGetSymbolAddress((void**)&t1, g_t1);
    cudaGetSymbolAddress((void**)&lp, g_lp);

    zero_k<<<(NTRAJ * NLAT + 255) / 256, 256>>>(h, NTRAJ * NLAT);

    float* probs  = out;
    float* states = out + (size_t)NSTEP * NTRAJ * NCLUS;

    for (int t = 0; t < NSTEP; t++) {
        // u,r gates: [h|x] @ [W_u | W_r], sigmoid; emits u and h*r
        gemm_k<ASRC_CONCAT, EPI_GATES><<<dim3(8, 32, 1), 128>>>(
            h, data, NLAT, W_u, W_r, NLAT, DCAT, DCAT,
            b_u, b_r, nullptr, nullptr, h, u, hr, t);
        // n gate + GRU blend: h = (1-u)*([h*r|x] @ W_n + b_n) + u*h
        gemm_k<ASRC_CONCAT, EPI_NEWH><<<dim3(8, 16, 1), 128>>>(
            hr, data, NLAT, W_n, nullptr, NLAT, DCAT, DCAT,
            b_n, nullptr, nullptr, u, h, nullptr, nullptr, t);
        // 2 Euler steps: h += sub * (tanh(h@W1+b1) @ W2 + b2)
        for (int e = 0; e < 2; e++) {
            ode1_k<<<dim3(64, 8), 256>>>(h, W1, t1p);
            tanhsum_k<<<(NTRAJ * NUNITS + 255) / 256, 256>>>(t1p, b1, t1);
            gemm_k<ASRC_PLAIN, EPI_EULER><<<dim3(8, 16, 1), 128>>>(
                t1, nullptr, NUNITS, W2, nullptr, NLAT, NUNITS, NUNITS,
                b2, b1, ts, nullptr, h, nullptr, nullptr, t);
        }
        // emission logits (K split by 4 for parallelism), then softmax + state copy
        gemm_k<ASRC_PLAIN, EPI_LOGITS><<<dim3(8, 4, 4), 128>>>(
            h, nullptr, NLAT, We, nullptr, NCLUS, NLAT, 256,
            nullptr, nullptr, nullptr, nullptr, nullptr, lp, nullptr, t);
        softmax_states_k<<<NTRAJ, 256>>>(lp, be, h,
            probs  + (size_t)t * NTRAJ * NCLUS,
            states + (size_t)t * NTRAJ * NLAT);
    }
}

// round 6
// speedup vs baseline: 1.4171x; 1.0008x over previous
#include <cuda_runtime.h>
#include <math.h>

#define NTRAJ 512
#define NTP 64
#define NSTEP 63
#define NIN 512
#define NLAT 1024
#define NUNITS 100
#define NCLUS 256
#define DCAT 1536

// ---------------- scratch (device globals: no runtime allocation) ----------
__device__ float g_h[NTRAJ * NLAT];           // recurrent state
__device__ float g_u[NTRAJ * NLAT];           // update gate
__device__ float g_hr[NTRAJ * NLAT];          // h * r
__device__ float g_t1p[8 * NTRAJ * NUNITS];   // K-split partials of h@W1
__device__ float g_t1[NTRAJ * NUNITS];        // tanh(h@W1+b1)
__device__ float g_lp[4 * NTRAJ * NCLUS];     // K-split partials of h@We

enum { ASRC_PLAIN = 0, ASRC_CONCAT = 1 };
enum { EPI_GATES = 0, EPI_NEWH = 1, EPI_EULER = 2, EPI_LOGITS = 3 };

#define BM 64
#define BN 64
#define BK 16

// Generic 64x64 tiled fp32 GEMM, 128 threads, 8x4 outputs per thread.
// Scalar FFMA inner loop (measured fastest on sm_103a; f32x2 regressed).
template <int ASRC, int EPI>
__global__ void __launch_bounds__(128) gemm_k(
    const float* __restrict__ A, const float* __restrict__ Ad, int lda,
    const float* __restrict__ B0, const float* __restrict__ B1, int ldb,
    int K, int KS,
    const float* __restrict__ bias0, const float* __restrict__ bias1,
    const float* __restrict__ ts, const float* __restrict__ uin,
    float* __restrict__ hbuf, float* __restrict__ out0, float* __restrict__ out1,
    int t)
{
    __shared__ __align__(16) float As[BK][68];   // padded, conflict-free
    __shared__ __align__(16) float Bs[BK][BN];

    const int tid = threadIdx.x;
    const int tx = tid & 15;       // 16 col groups * 4 cols
    const int ty = tid >> 4;       // 8 row groups * 8 rows
    const int r0 = blockIdx.x * BM;
    const int c0 = blockIdx.y * BN;

    const float* Bp = B0;
    int cb = c0;
    if (EPI == EPI_GATES) {                 // N=2048: left half = W_u, right = W_r
        if (c0 >= NLAT) { Bp = B1; cb = c0 - NLAT; }
    }

    float acc[8][4];
#pragma unroll
    for (int i = 0; i < 8; i++)
#pragma unroll
        for (int j = 0; j < 4; j++) acc[i][j] = 0.f;

    const int k0 = blockIdx.z * KS;
    const int k1 = (k0 + KS < K) ? (k0 + KS) : K;

    for (int kk = k0; kk < k1; kk += BK) {
        // ---- load A tile (transposed into shared) ----
#pragma unroll
        for (int i = 0; i < 8; i++) {
            int idx = tid + i * 128;
            int m = idx >> 4, kq = idx & 15;
            int gk = kk + kq;
            float v = 0.f;
            if (ASRC == ASRC_PLAIN) {
                if (gk < k1) v = A[(r0 + m) * lda + gk];
            } else { // ASRC_CONCAT: A = [state(512x1024) | data[:, t, :](512x512)]
                if (gk < NLAT) v = A[(r0 + m) * NLAT + gk];
                else           v = Ad[(r0 + m) * (NTP * NIN) + t * NIN + (gk - NLAT)];
            }
            As[kq][m] = v;
        }
        // ---- load B tile ----
#pragma unroll
        for (int i = 0; i < 8; i++) {
            int idx = tid + i * 128;
            int kq = idx >> 6, n = idx & 63;
            int gk = kk + kq;
            Bs[kq][n] = (gk < k1) ? Bp[gk * ldb + cb + n] : 0.f;
        }
        __syncthreads();
        // ---- scalar FMA ----
#pragma unroll
        for (int k = 0; k < BK; k++) {
            float4 a0 = *(const float4*)&As[k][ty * 8];
            float4 a1 = *(const float4*)&As[k][ty * 8 + 4];
            float4 b  = *(const float4*)&Bs[k][tx * 4];
            float av[8] = {a0.x, a0.y, a0.z, a0.w, a1.x, a1.y, a1.z, a1.w};
            float bv[4] = {b.x, b.y, b.z, b.w};
#pragma unroll
            for (int i = 0; i < 8; i++)
#pragma unroll
                for (int j = 0; j < 4; j++)
                    acc[i][j] += av[i] * bv[j];
        }
        __syncthreads();
    }

    // ---- epilogue ----
#pragma unroll
    for (int i = 0; i < 8; i++) {
        int row = r0 + ty * 8 + i;
#pragma unroll
        for (int j = 0; j < 4; j++) {
            int col = c0 + tx * 4 + j;
            float v = acc[i][j];
            if (EPI == EPI_GATES) {
                float b = (col < NLAT) ? bias0[col] : bias1[col - NLAT];
                float s = 1.f / (1.f + expf(-(v + b)));
                if (col < NLAT) {
                    out0[row * NLAT + col] = s;                       // u gate
                } else {
                    int c = col - NLAT;
                    out1[row * NLAT + c] = hbuf[row * NLAT + c] * s;  // h*r
                }
            } else if (EPI == EPI_NEWH) {
                float n  = v + bias0[col];
                float uu = uin[row * NLAT + col];
                float ho = hbuf[row * NLAT + col];
                hbuf[row * NLAT + col] = (1.f - uu) * n + uu * ho;    // GRU blend
            } else if (EPI == EPI_EULER) {
                float sub = 0.5f * (ts[t + 1] - ts[t]);               // dt / (N_INTER-1)
                hbuf[row * NLAT + col] += sub * (v + bias0[col]);
            } else { // EPI_LOGITS: write K-split partial (bias added in softmax)
                out0[blockIdx.z * (NTRAJ * NCLUS) + row * NCLUS + col] = v;
            }
        }
    }
}

// h@W1 partial GEMM: grid (64 row-blocks of 8, 8 K-splits of 128). N=100.
__global__ void __launch_bounds__(256) ode1_k(const float* __restrict__ h,
                                              const float* __restrict__ W1,
                                              float* __restrict__ t1p)
{
    __shared__ float As[16][9];     // padded: conflict-free stores
    __shared__ float Ws[16][128];
    const int tid = threadIdx.x;
    const int tx = tid & 127;       // col (active < 100)
    const int ty = tid >> 7;        // 0..1, 4 rows each
    const int r0 = blockIdx.x * 8;
    const int ks = blockIdx.y;
    float acc[4] = {0.f, 0.f, 0.f, 0.f};

    for (int kk = ks * 128; kk < ks * 128 + 128; kk += 16) {
        if (tid < 128) {
            int m = tid >> 4, kq = tid & 15;
            As[kq][m] = h[(r0 + m) * NLAT + kk + kq];
        }
#pragma unroll
        for (int j = 0; j < 8; j++) {
            int kq = ty * 8 + j;
            Ws[kq][tx] = (tx < NUNITS) ? W1[(kk + kq) * NUNITS + tx] : 0.f;
        }
        __syncthreads();
        if (tx < NUNITS) {
#pragma unroll
            for (int kq = 0; kq < 16; kq++) {
                float w = Ws[kq][tx];
#pragma unroll
                for (int r = 0; r < 4; r++)
                    acc[r] += As[kq][ty * 4 + r] * w;
            }
        }
        __syncthreads();
    }
    if (tx < NUNITS) {
#pragma unroll
        for (int r = 0; r < 4; r++)
            t1p[ks * (NTRAJ * NUNITS) + (r0 + ty * 4 + r) * NUNITS + tx] = acc[r];
    }
}

// t1 = tanh(b1 + sum of 8 K-split partials)
__global__ void __launch_bounds__(256) tanhsum_k(const float* __restrict__ t1p,
                                                 const float* __restrict__ b1,
                                                 float* __restrict__ t1)
{
    int i = blockIdx.x * 256 + threadIdx.x;
    if (i >= NTRAJ * NUNITS) return;
    int col = i % NUNITS;
    float s = b1[col];
#pragma unroll
    for (int p = 0; p < 8; p++) s += t1p[p * (NTRAJ * NUNITS) + i];
    t1[i] = tanhf(s);
}

// Sum logits partials + bias, softmax over 256 clusters, and copy states out.
__global__ void __launch_bounds__(256) softmax_states_k(
    const float* __restrict__ lp, const float* __restrict__ be,
    const float* __restrict__ h,
    float* __restrict__ prob_out, float* __restrict__ state_out)
{
    const int row = blockIdx.x;
    const int tid = threadIdx.x;
    __shared__ float smax[8], ssum[8];

    float v = be[tid];
#pragma unroll
    for (int s = 0; s < 4; s++) v += lp[s * (NTRAJ * NCLUS) + row * NCLUS + tid];

    float m = v;
#pragma unroll
    for (int o = 16; o > 0; o >>= 1) m = fmaxf(m, __shfl_xor_sync(0xffffffffu, m, o));
    if ((tid & 31) == 0) smax[tid >> 5] = m;
    __syncthreads();
    float mx = smax[0];
#pragma unroll
    for (int w = 1; w < 8; w++) mx = fmaxf(mx, smax[w]);

    float e = expf(v - mx);
    float s = e;
#pragma unroll
    for (int o = 16; o > 0; o >>= 1) s += __shfl_xor_sync(0xffffffffu, s, o);
    if ((tid & 31) == 0) ssum[tid >> 5] = s;
    __syncthreads();
    float tot = 0.f;
#pragma unroll
    for (int w = 0; w < 8; w++) tot += ssum[w];

    prob_out[row * NCLUS + tid] = e / tot;
#pragma unroll
    for (int i = 0; i < 4; i++)
        state_out[row * NLAT + i * 256 + tid] = h[row * NLAT + i * 256 + tid];
}

__global__ void zero_k(float* __restrict__ p, int n)
{
    int i = blockIdx.x * blockDim.x + threadIdx.x;
    if (i < n) p[i] = 0.f;
}

extern "C" void kernel_launch(void* const* d_in, const int* in_sizes, int n_in,
                              void* d_out, int out_size)
{
    const float* data = (const float*)d_in[0];
    const float* ts   = (const float*)d_in[1];
    const float* W_u  = (const float*)d_in[2];
    const float* b_u  = (const float*)d_in[3];
    const float* W_r  = (const float*)d_in[4];
    const float* b_r  = (const float*)d_in[5];
    const float* W_n  = (const float*)d_in[6];
    const float* b_n  = (const float*)d_in[7];
    const float* W1   = (const float*)d_in[8];
    const float* b1   = (const float*)d_in[9];
    const float* W2   = (const float*)d_in[10];
    const float* b2   = (const float*)d_in[11];
    const float* We   = (const float*)d_in[12];
    const float* be   = (const float*)d_in[13];
    float* out = (float*)d_out;

    float *h, *u, *hr, *t1p, *t1, *lp;
    cudaGetSymbolAddress((void**)&h, g_h);
    cudaGetSymbolAddress((void**)&u, g_u);
    cudaGetSymbolAddress((void**)&hr, g_hr);
    cudaGetSymbolAddress((void**)&t1p, g_t1p);
    cudaGetSymbolAddress((void**)&t1, g_t1);
    cudaGetSymbolAddress((void**)&lp, g_lp);

    zero_k<<<(NTRAJ * NLAT + 255) / 256, 256>>>(h, NTRAJ * NLAT);

    float* probs  = out;
    float* states = out + (size_t)NSTEP * NTRAJ * NCLUS;

    for (int t = 0; t < NSTEP; t++) {
        // u,r gates: [h|x] @ [W_u | W_r], sigmoid; emits u and h*r
        gemm_k<ASRC_CONCAT, EPI_GATES><<<dim3(8, 32, 1), 128>>>(
            h, data, NLAT, W_u, W_r, NLAT, DCAT, DCAT,
            b_u, b_r, nullptr, nullptr, h, u, hr, t);
        // n gate + GRU blend: h = (1-u)*([h*r|x] @ W_n + b_n) + u*h
        gemm_k<ASRC_CONCAT, EPI_NEWH><<<dim3(8, 16, 1), 128>>>(
            hr, data, NLAT, W_n, nullptr, NLAT, DCAT, DCAT,
            b_n, nullptr, nullptr, u, h, nullptr, nullptr, t);
        // 2 Euler steps: h += sub * (tanh(h@W1+b1) @ W2 + b2)
        for (int e = 0; e < 2; e++) {
            ode1_k<<<dim3(64, 8), 256>>>(h, W1, t1p);
            tanhsum_k<<<(NTRAJ * NUNITS + 255) / 256, 256>>>(t1p, b1, t1);
            gemm_k<ASRC_PLAIN, EPI_EULER><<<dim3(8, 16, 1), 128>>>(
                t1, nullptr, NUNITS, W2, nullptr, NLAT, NUNITS, NUNITS,
                b2, b1, ts, nullptr, h, nullptr, nullptr, t);
        }
        // emission logits (K split by 4 for parallelism), then softmax + state copy
        gemm_k<ASRC_PLAIN, EPI_LOGITS><<<dim3(8, 4, 4), 128>>>(
            h, nullptr, NLAT, We, nullptr, NCLUS, NLAT, 256,
            nullptr, nullptr, nullptr, nullptr, nullptr, lp, nullptr, t);
        softmax_states_k<<<NTRAJ, 256>>>(lp, be, h,
            probs  + (size_t)t * NTRAJ * NCLUS,
            states + (size_t)t * NTRAJ * NLAT);
    }
}

// round 14
// speedup vs baseline: 1.4814x; 1.0454x over previous
#include <cuda_runtime.h>
#include <cuda_bf16.h>
#include <math.h>
#include <stdint.h>

#define NTRAJ 512
#define NTP   64
#define NSTEP 63
#define NIN   512
#define NLAT  1024
#define NUNITS 100
#define NCLUS 256
#define DCAT  1536
#define KODE  128

typedef __nv_bfloat16 bf16;

// ---------------- scratch: 3-term bf16 splits of every GEMM operand --------
__device__ __align__(16) float g_h[NTRAJ * NLAT];
__device__ __align__(16) float g_u[NTRAJ * NLAT];
__device__ __align__(16) bf16  g_h1[NTRAJ * NLAT],  g_h2[NTRAJ * NLAT],  g_h3[NTRAJ * NLAT];
__device__ __align__(16) bf16  g_hr1[NTRAJ * NLAT], g_hr2[NTRAJ * NLAT], g_hr3[NTRAJ * NLAT];
__device__ __align__(16) bf16  g_t11[NTRAJ * KODE], g_t12[NTRAJ * KODE], g_t13[NTRAJ * KODE];
__device__ __align__(16) float g_t1p[4 * NTRAJ * KODE];
__device__ __align__(16) float g_lp[2 * NTRAJ * NCLUS];
__device__ __align__(16) bf16  g_X1[NTRAJ * NTP * NIN], g_X2[NTRAJ * NTP * NIN], g_X3[NTRAJ * NTP * NIN];
__device__ __align__(16) bf16  g_Wg1[2048 * DCAT], g_Wg2[2048 * DCAT], g_Wg3[2048 * DCAT];
__device__ __align__(16) bf16  g_Wn1[NLAT * DCAT], g_Wn2[NLAT * DCAT], g_Wn3[NLAT * DCAT];
__device__ __align__(16) bf16  g_We1[NCLUS * NLAT], g_We2[NCLUS * NLAT], g_We3[NCLUS * NLAT];
__device__ __align__(16) bf16  g_W11[KODE * NLAT], g_W12[KODE * NLAT], g_W13[KODE * NLAT];
__device__ __align__(16) bf16  g_W21[NLAT * KODE], g_W22[NLAT * KODE], g_W23[NLAT * KODE];

__device__ __forceinline__ uint32_t smem_u32(const void* p) {
    uint32_t a;
    asm("{ .reg .u64 t; cvta.to.shared.u64 t, %1; cvt.u32.u64 %0, t; }" : "=r"(a) : "l"(p));
    return a;
}
__device__ __forceinline__ void ldm_x4(uint32_t* r, uint32_t addr) {
    asm volatile("ldmatrix.sync.aligned.m8n8.x4.shared.b16 {%0,%1,%2,%3}, [%4];"
                 : "=r"(r[0]), "=r"(r[1]), "=r"(r[2]), "=r"(r[3]) : "r"(addr));
}
__device__ __forceinline__ void mma16816(float* d, const uint32_t* a, const uint32_t* b) {
    asm volatile("mma.sync.aligned.m16n8k16.row.col.f32.bf16.bf16.f32 "
                 "{%0,%1,%2,%3}, {%4,%5,%6,%7}, {%8,%9}, {%0,%1,%2,%3};"
                 : "+f"(d[0]), "+f"(d[1]), "+f"(d[2]), "+f"(d[3])
                 : "r"(a[0]), "r"(a[1]), "r"(a[2]), "r"(a[3]), "r"(b[0]), "r"(b[1]));
}

__device__ __forceinline__ float sigm(float x) { return 1.f / (1.f + expf(-x)); }

__device__ __forceinline__ void split3_1(float v, bf16& o1, bf16& o2, bf16& o3) {
    o1 = __float2bfloat16(v);
    float r1 = v - __bfloat162float(o1);
    o2 = __float2bfloat16(r1);
    float r2 = r1 - __bfloat162float(o2);
    o3 = __float2bfloat16(r2);
}
__device__ __forceinline__ void split3_2(float v0, float v1,
                                         bf16* D1, bf16* D2, bf16* D3, size_t idx) {
    bf16 a1, a2, a3, b1, b2, b3;
    split3_1(v0, a1, a2, a3);
    split3_1(v1, b1, b2, b3);
    __nv_bfloat162 p1, p2, p3;
    p1.x = a1; p1.y = b1; p2.x = a2; p2.y = b2; p3.x = a3; p3.y = b3;
    *(__nv_bfloat162*)&D1[idx] = p1;
    *(__nv_bfloat162*)&D2[idx] = p2;
    *(__nv_bfloat162*)&D3[idx] = p3;
}

enum { EPI_GATES = 0, EPI_NEWH = 1, EPI_ODE1 = 2, EPI_EULER = 3, EPI_LOGITS = 4 };

// bf16x6 GEMM on mma.sync (HMMA) with TWO-LEVEL ACCUMULATION:
// per k16 step the 6 split-MMAs go into a fresh zeroed fragment (short RZ chain),
// which is then promoted into the master fp32 accumulator with RN adds.
// C[m,n] = sum_k A[m,k]*B[n,k]. Block 128 thr = 4 warps (2x2), tile 64x64, K-chunk 32.
template <int EPI>
__global__ void __launch_bounds__(128) tgemm_k(
    const bf16* __restrict__ A0a, const bf16* __restrict__ A0b, const bf16* __restrict__ A0c, int lda0,
    const bf16* __restrict__ A1a, const bf16* __restrict__ A1b, const bf16* __restrict__ A1c, int lda1, int K0,
    const bf16* __restrict__ Ba, const bf16* __restrict__ Bb, const bf16* __restrict__ Bc, int ldb,
    int kseg, int nch,
    const float* __restrict__ bias0, const float* __restrict__ bias1,
    const float* __restrict__ ts, int t,
    const float* __restrict__ uptr, float* __restrict__ hptr,
    bf16* __restrict__ o1, bf16* __restrict__ o2, bf16* __restrict__ o3,
    float* __restrict__ outF)
{
    __shared__ __align__(16) bf16 sm[6 * 64 * 40];   // 6 matrices, 80B row stride
    const uint32_t sb = smem_u32(sm);
    const uint32_t OA1 = 0, OA2 = 5120, OA3 = 10240, OB1 = 15360, OB2 = 20480, OB3 = 25600;

    const int tid = threadIdx.x, wid = tid >> 5, lane = tid & 31;
    const int m0 = blockIdx.x * 64, n0 = blockIdx.y * 64;
    const int kbase = blockIdx.z * kseg;
    const int mbL = (wid >> 1) * 32;
    const int nbL = (wid & 1) * 32;

    float acc[2][4][4];
#pragma unroll
    for (int i = 0; i < 2; i++)
#pragma unroll
        for (int j = 0; j < 4; j++)
#pragma unroll
            for (int q = 0; q < 4; q++) acc[i][j][q] = 0.f;

    const int lr  = lane & 15;
    const int lkb = (lane >> 4) * 16;

    for (int c = 0; c < nch; c++) {
        const int gk = kbase + c * 32;
        const bf16 *aa, *ab, *ac; int lA, ka;
        if (gk < K0) { aa = A0a; ab = A0b; ac = A0c; lA = lda0; ka = gk; }
        else         { aa = A1a; ab = A1b; ac = A1c; lA = lda1; ka = gk - K0; }
        // ---- stage chunk: 64x32 for all 6 matrices ----
#pragma unroll
        for (int i = 0; i < 2; i++) {
            int slot = tid + i * 128;            // 256 slots = 64 rows * 4 vec8
            int row = slot >> 2, c8 = slot & 3;
            uint32_t so = (uint32_t)(row * 80 + c8 * 16);
            size_t aoff = (size_t)(m0 + row) * lA + ka;
            size_t boff = (size_t)(n0 + row) * ldb + gk;
            uint4 v;
            v = *((const uint4*)(aa + aoff) + c8); *(uint4*)((char*)sm + OA1 + so) = v;
            v = *((const uint4*)(ab + aoff) + c8); *(uint4*)((char*)sm + OA2 + so) = v;
            v = *((const uint4*)(ac + aoff) + c8); *(uint4*)((char*)sm + OA3 + so) = v;
            v = *((const uint4*)(Ba + boff) + c8); *(uint4*)((char*)sm + OB1 + so) = v;
            v = *((const uint4*)(Bb + boff) + c8); *(uint4*)((char*)sm + OB2 + so) = v;
            v = *((const uint4*)(Bc + boff) + c8); *(uint4*)((char*)sm + OB3 + so) = v;
        }
        __syncthreads();
        // ---- 2 k16 steps ----
#pragma unroll
        for (int kh = 0; kh < 2; kh++) {
            uint32_t a1[2][4], a2[2][4], a3[2][4], b1[2][4], b2[2][4], b3[2][4];
#pragma unroll
            for (int tm = 0; tm < 2; tm++) {
                uint32_t ro = (uint32_t)((mbL + tm * 16 + lr) * 80 + kh * 32 + lkb);
                ldm_x4(a1[tm], sb + OA1 + ro);
                ldm_x4(a2[tm], sb + OA2 + ro);
                ldm_x4(a3[tm], sb + OA3 + ro);
            }
#pragma unroll
            for (int p = 0; p < 2; p++) {
                uint32_t ro = (uint32_t)((nbL + p * 16 + lr) * 80 + kh * 32 + lkb);
                ldm_x4(b1[p], sb + OB1 + ro);
                ldm_x4(b2[p], sb + OB2 + ro);
                ldm_x4(b3[p], sb + OB3 + ro);
            }
#pragma unroll
            for (int tm = 0; tm < 2; tm++)
#pragma unroll
                for (int tn = 0; tn < 4; tn++) {
                    int p = tn >> 1, q = tn & 1;
                    uint32_t B1f[2] = { b1[p][q], b1[p][q + 2] };
                    uint32_t B2f[2] = { b2[p][q], b2[p][q + 2] };
                    uint32_t B3f[2] = { b3[p][q], b3[p][q + 2] };
                    // fresh fragment: short RZ chain inside the tensor core
                    float m4[4] = {0.f, 0.f, 0.f, 0.f};
                    mma16816(m4, a3[tm], B1f);
                    mma16816(m4, a1[tm], B3f);
                    mma16816(m4, a2[tm], B2f);
                    mma16816(m4, a2[tm], B1f);
                    mma16816(m4, a1[tm], B2f);
                    mma16816(m4, a1[tm], B1f);
                    // promote to master accumulator with RN adds (fma pipe, free)
                    acc[tm][tn][0] += m4[0];
                    acc[tm][tn][1] += m4[1];
                    acc[tm][tn][2] += m4[2];
                    acc[tm][tn][3] += m4[3];
                }
        }
        __syncthreads();
    }

    // ---- epilogue: c0,c1 -> row lane>>2, cols 2*(lane&3)+{0,1}; c2,c3 -> row+8
    const int er = lane >> 2, ec = (lane & 3) * 2;
#pragma unroll
    for (int tm = 0; tm < 2; tm++)
#pragma unroll
        for (int tn = 0; tn < 4; tn++)
#pragma unroll
            for (int half = 0; half < 2; half++) {
                int row = m0 + mbL + tm * 16 + er + half * 8;
                int col = n0 + nbL + tn * 8 + ec;
                float v0 = acc[tm][tn][half * 2 + 0];
                float v1 = acc[tm][tn][half * 2 + 1];
                if (EPI == EPI_GATES) {
                    if (n0 < NLAT) {                    // u half
                        float2 o;
                        o.x = sigm(v0 + bias0[col]);
                        o.y = sigm(v1 + bias0[col + 1]);
                        *(float2*)&outF[(size_t)row * NLAT + col] = o;
                    } else {                            // r half -> hr = h * sigmoid
                        int cc = col - NLAT;
                        float2 hv = *(const float2*)&hptr[(size_t)row * NLAT + cc];
                        float r0 = hv.x * sigm(v0 + bias1[cc]);
                        float r1 = hv.y * sigm(v1 + bias1[cc + 1]);
                        split3_2(r0, r1, o1, o2, o3, (size_t)row * NLAT + cc);
                    }
                } else if (EPI == EPI_NEWH) {
                    float2 uu = *(const float2*)&uptr[(size_t)row * NLAT + col];
                    float2 ho = *(const float2*)&hptr[(size_t)row * NLAT + col];
                    float w0 = (1.f - uu.x) * (v0 + bias0[col])     + uu.x * ho.x;
                    float w1 = (1.f - uu.y) * (v1 + bias0[col + 1]) + uu.y * ho.y;
                    *(float2*)&hptr[(size_t)row * NLAT + col] = make_float2(w0, w1);
                    split3_2(w0, w1, o1, o2, o3, (size_t)row * NLAT + col);
                } else if (EPI == EPI_ODE1) {
                    *(float2*)&outF[(size_t)blockIdx.z * (NTRAJ * KODE)
                                    + (size_t)row * KODE + col] = make_float2(v0, v1);
                } else if (EPI == EPI_EULER) {
                    float sub = 0.5f * (ts[t + 1] - ts[t]);
                    float2 ho = *(const float2*)&hptr[(size_t)row * NLAT + col];
                    float w0 = ho.x + sub * (v0 + bias0[col]);
                    float w1 = ho.y + sub * (v1 + bias0[col + 1]);
                    *(float2*)&hptr[(size_t)row * NLAT + col] = make_float2(w0, w1);
                    split3_2(w0, w1, o1, o2, o3, (size_t)row * NLAT + col);
                } else { // EPI_LOGITS
                    *(float2*)&outF[(size_t)blockIdx.z * (NTRAJ * NCLUS)
                                    + (size_t)row * NCLUS + col] = make_float2(v0, v1);
                }
            }
}

// transpose + 3-split: out[n][k] = (k<Ksrc && n<Nsrc) ? src[k][n] : 0
__global__ void tsplit_k(const float* __restrict__ src, int Ksrc, int Nsrc,
                         bf16* __restrict__ d1, bf16* __restrict__ d2,
                         bf16* __restrict__ d3, int Kout)
{
    __shared__ float tile[32][33];
    const int kb = blockIdx.x * 32, nb = blockIdx.y * 32;
    const int tx = threadIdx.x, ty = threadIdx.y;
    int k = kb + ty, n = nb + tx;
    tile[ty][tx] = (k < Ksrc && n < Nsrc) ? src[(size_t)k * Nsrc + n] : 0.f;
    __syncthreads();
    int on = nb + ty, ok = kb + tx;
    float v = tile[tx][ty];
    bf16 a, b, c;
    split3_1(v, a, b, c);
    d1[(size_t)on * Kout + ok] = a;
    d2[(size_t)on * Kout + ok] = b;
    d3[(size_t)on * Kout + ok] = c;
}

__global__ void splitx_k(const float* __restrict__ d,
                         bf16* __restrict__ x1, bf16* __restrict__ x2, bf16* __restrict__ x3)
{
    size_t i = (size_t)blockIdx.x * 256 + threadIdx.x;
    bf16 a, b, c;
    split3_1(d[i], a, b, c);
    x1[i] = a; x2[i] = b; x3[i] = c;
}

__global__ void zeroh_k(float* __restrict__ h,
                        bf16* __restrict__ h1, bf16* __restrict__ h2, bf16* __restrict__ h3)
{
    int i = blockIdx.x * 256 + threadIdx.x;
    h[i] = 0.f;
    bf16 z = __float2bfloat16(0.f);
    h1[i] = z; h2[i] = z; h3[i] = z;
}

__global__ void tanhsplit_k(const float* __restrict__ t1p, const float* __restrict__ b1,
                            bf16* __restrict__ t1, bf16* __restrict__ t2, bf16* __restrict__ t3)
{
    int i = blockIdx.x * 256 + threadIdx.x;   // 65536 total
    int c = i & (KODE - 1);
    float s = 0.f;
    if (c < NUNITS) {
        s = b1[c];
#pragma unroll
        for (int z = 0; z < 4; z++) s += t1p[z * (NTRAJ * KODE) + i];
        s = tanhf(s);
    }
    bf16 a, b, d;
    split3_1(s, a, b, d);
    t1[i] = a; t2[i] = b; t3[i] = d;
}

__global__ void __launch_bounds__(256) softmax_states_k(
    const float* __restrict__ lp, const float* __restrict__ be,
    const float* __restrict__ h,
    float* __restrict__ prob_out, float* __restrict__ state_out)
{
    const int row = blockIdx.x;
    const int tid = threadIdx.x;
    __shared__ float smax[8], ssum[8];

    float v = be[tid] + lp[(size_t)row * NCLUS + tid]
                      + lp[(size_t)NTRAJ * NCLUS + (size_t)row * NCLUS + tid];
    float m = v;
#pragma unroll
    for (int o = 16; o > 0; o >>= 1) m = fmaxf(m, __shfl_xor_sync(0xffffffffu, m, o));
    if ((tid & 31) == 0) smax[tid >> 5] = m;
    __syncthreads();
    float mx = smax[0];
#pragma unroll
    for (int w = 1; w < 8; w++) mx = fmaxf(mx, smax[w]);

    float e = expf(v - mx);
    float s = e;
#pragma unroll
    for (int o = 16; o > 0; o >>= 1) s += __shfl_xor_sync(0xffffffffu, s, o);
    if ((tid & 31) == 0) ssum[tid >> 5] = s;
    __syncthreads();
    float tot = 0.f;
#pragma unroll
    for (int w = 0; w < 8; w++) tot += ssum[w];

    prob_out[(size_t)row * NCLUS + tid] = e / tot;
#pragma unroll
    for (int i = 0; i < 4; i++)
        state_out[(size_t)row * NLAT + i * 256 + tid] = h[(size_t)row * NLAT + i * 256 + tid];
}

extern "C" void kernel_launch(void* const* d_in, const int* in_sizes, int n_in,
                              void* d_out, int out_size)
{
    const float* data = (const float*)d_in[0];
    const float* ts   = (const float*)d_in[1];
    const float* W_u  = (const float*)d_in[2];
    const float* b_u  = (const float*)d_in[3];
    const float* W_r  = (const float*)d_in[4];
    const float* b_r  = (const float*)d_in[5];
    const float* W_n  = (const float*)d_in[6];
    const float* b_n  = (const float*)d_in[7];
    const float* W1   = (const float*)d_in[8];
    const float* b1   = (const float*)d_in[9];
    const float* W2   = (const float*)d_in[10];
    const float* b2   = (const float*)d_in[11];
    const float* We   = (const float*)d_in[12];
    const float* be   = (const float*)d_in[13];
    float* out = (float*)d_out;

    float *h, *u, *t1p, *lp;
    bf16 *h1, *h2, *h3, *hr1, *hr2, *hr3, *t11, *t12, *t13, *X1, *X2, *X3;
    bf16 *Wg1, *Wg2, *Wg3, *Wn1, *Wn2, *Wn3, *We1, *We2, *We3;
    bf16 *W11, *W12, *W13, *W21, *W22, *W23;
    cudaGetSymbolAddress((void**)&h, g_h);     cudaGetSymbolAddress((void**)&u, g_u);
    cudaGetSymbolAddress((void**)&t1p, g_t1p); cudaGetSymbolAddress((void**)&lp, g_lp);
    cudaGetSymbolAddress((void**)&h1, g_h1);   cudaGetSymbolAddress((void**)&h2, g_h2);
    cudaGetSymbolAddress((void**)&h3, g_h3);
    cudaGetSymbolAddress((void**)&hr1, g_hr1); cudaGetSymbolAddress((void**)&hr2, g_hr2);
    cudaGetSymbolAddress((void**)&hr3, g_hr3);
    cudaGetSymbolAddress((void**)&t11, g_t11); cudaGetSymbolAddress((void**)&t12, g_t12);
    cudaGetSymbolAddress((void**)&t13, g_t13);
    cudaGetSymbolAddress((void**)&X1, g_X1);   cudaGetSymbolAddress((void**)&X2, g_X2);
    cudaGetSymbolAddress((void**)&X3, g_X3);
    cudaGetSymbolAddress((void**)&Wg1, g_Wg1); cudaGetSymbolAddress((void**)&Wg2, g_Wg2);
    cudaGetSymbolAddress((void**)&Wg3, g_Wg3);
    cudaGetSymbolAddress((void**)&Wn1, g_Wn1); cudaGetSymbolAddress((void**)&Wn2, g_Wn2);
    cudaGetSymbolAddress((void**)&Wn3, g_Wn3);
    cudaGetSymbolAddress((void**)&We1, g_We1); cudaGetSymbolAddress((void**)&We2, g_We2);
    cudaGetSymbolAddress((void**)&We3, g_We3);
    cudaGetSymbolAddress((void**)&W11, g_W11); cudaGetSymbolAddress((void**)&W12, g_W12);
    cudaGetSymbolAddress((void**)&W13, g_W13);
    cudaGetSymbolAddress((void**)&W21, g_W21); cudaGetSymbolAddress((void**)&W22, g_W22);
    cudaGetSymbolAddress((void**)&W23, g_W23);

    splitx_k<<<65536, 256>>>(data, X1, X2, X3);
    tsplit_k<<<dim3(DCAT/32, NLAT/32),  dim3(32,32)>>>(W_u, DCAT, NLAT, Wg1, Wg2, Wg3, DCAT);
    tsplit_k<<<dim3(DCAT/32, NLAT/32),  dim3(32,32)>>>(W_r, DCAT, NLAT,
        Wg1 + (size_t)NLAT*DCAT, Wg2 + (size_t)NLAT*DCAT, Wg3 + (size_t)NLAT*DCAT, DCAT);
    tsplit_k<<<dim3(DCAT/32, NLAT/32),  dim3(32,32)>>>(W_n, DCAT, NLAT, Wn1, Wn2, Wn3, DCAT);
    tsplit_k<<<dim3(NLAT/32, NCLUS/32), dim3(32,32)>>>(We, NLAT, NCLUS, We1, We2, We3, NLAT);
    tsplit_k<<<dim3(NLAT/32, KODE/32),  dim3(32,32)>>>(W1, NLAT, NUNITS, W11, W12, W13, NLAT);
    tsplit_k<<<dim3(KODE/32, NLAT/32),  dim3(32,32)>>>(W2, NUNITS, NLAT, W21, W22, W23, KODE);
    zeroh_k<<<2048, 256>>>(h, h1, h2, h3);

    float* probs  = out;
    float* states = out + (size_t)NSTEP * NTRAJ * NCLUS;
    const int BIGK = 1 << 30;

    for (int t = 0; t < NSTEP; t++) {
        // u,r gates: [h|x] @ [W_u|W_r]^T; emits u and split3(h*r)
        tgemm_k<EPI_GATES><<<dim3(8, 32, 1), 128>>>(
            h1, h2, h3, NLAT,
            X1 + (size_t)t*NIN, X2 + (size_t)t*NIN, X3 + (size_t)t*NIN, NTP*NIN, NLAT,
            Wg1, Wg2, Wg3, DCAT, DCAT, 48,
            b_u, b_r, nullptr, 0, nullptr, h, hr1, hr2, hr3, u);
        // n + GRU blend: h = (1-u)*([h*r|x]@W_n + b_n) + u*h; emits split3(h)
        tgemm_k<EPI_NEWH><<<dim3(8, 16, 1), 128>>>(
            hr1, hr2, hr3, NLAT,
            X1 + (size_t)t*NIN, X2 + (size_t)t*NIN, X3 + (size_t)t*NIN, NTP*NIN, NLAT,
            Wn1, Wn2, Wn3, DCAT, DCAT, 48,
            b_n, nullptr, nullptr, 0, u, h, h1, h2, h3, nullptr);
        // 2 Euler steps: h += sub * (tanh(h@W1+b1) @ W2 + b2)
        for (int e = 0; e < 2; e++) {
            tgemm_k<EPI_ODE1><<<dim3(8, 2, 4), 128>>>(
                h1, h2, h3, NLAT, nullptr, nullptr, nullptr, 0, BIGK,
                W11, W12, W13, NLAT, 256, 8,
                nullptr, nullptr, nullptr, 0, nullptr, nullptr,
                nullptr, nullptr, nullptr, t1p);
            tanhsplit_k<<<256, 256>>>(t1p, b1, t11, t12, t13);
            tgemm_k<EPI_EULER><<<dim3(8, 16, 1), 128>>>(
                t11, t12, t13, KODE, nullptr, nullptr, nullptr, 0, BIGK,
                W21, W22, W23, KODE, KODE, 4,
                b2, nullptr, ts, t, nullptr, h, h1, h2, h3, nullptr);
        }
        // emission logits (K split x2), then softmax + state copy
        tgemm_k<EPI_LOGITS><<<dim3(8, 4, 2), 128>>>(
            h1, h2, h3, NLAT, nullptr, nullptr, nullptr, 0, BIGK,
            We1, We2, We3, NLAT, 512, 16,
            nullptr, nullptr, nullptr, 0, nullptr, nullptr,
            nullptr, nullptr, nullptr, lp);
        softmax_states_k<<<NTRAJ, 256>>>(lp, be, h,
            probs  + (size_t)t * NTRAJ * NCLUS,
            states + (size_t)t * NTRAJ * NLAT);
    }
}

// round 15
// speedup vs baseline: 1.6394x; 1.1067x over previous
#include <cuda_runtime.h>
#include <cuda_bf16.h>
#include <math.h>
#include <stdint.h>

#define NTRAJ 512
#define NTP   64
#define NSTEP 63
#define NIN   512
#define NLAT  1024
#define NUNITS 100
#define NCLUS 256
#define DCAT  1536
#define KODE  128

typedef __nv_bfloat16 bf16;

// ---------------- scratch: 3-term bf16 splits of every GEMM operand --------
__device__ __align__(16) float g_h[NTRAJ * NLAT];
__device__ __align__(16) float g_u[NTRAJ * NLAT];
__device__ __align__(16) bf16  g_h1[NTRAJ * NLAT],  g_h2[NTRAJ * NLAT],  g_h3[NTRAJ * NLAT];
__device__ __align__(16) bf16  g_hr1[NTRAJ * NLAT], g_hr2[NTRAJ * NLAT], g_hr3[NTRAJ * NLAT];
__device__ __align__(16) bf16  g_t11[NTRAJ * KODE], g_t12[NTRAJ * KODE], g_t13[NTRAJ * KODE];
__device__ __align__(16) float g_t1p[4 * NTRAJ * KODE];
__device__ __align__(16) float g_lp[2 * NTRAJ * NCLUS];
__device__ __align__(16) bf16  g_X1[NTRAJ * NTP * NIN], g_X2[NTRAJ * NTP * NIN], g_X3[NTRAJ * NTP * NIN];
__device__ __align__(16) bf16  g_Wg1[2048 * DCAT], g_Wg2[2048 * DCAT], g_Wg3[2048 * DCAT];
__device__ __align__(16) bf16  g_Wn1[NLAT * DCAT], g_Wn2[NLAT * DCAT], g_Wn3[NLAT * DCAT];
__device__ __align__(16) bf16  g_We1[NCLUS * NLAT], g_We2[NCLUS * NLAT], g_We3[NCLUS * NLAT];
__device__ __align__(16) bf16  g_W11[KODE * NLAT], g_W12[KODE * NLAT], g_W13[KODE * NLAT];
__device__ __align__(16) bf16  g_W21[NLAT * KODE], g_W22[NLAT * KODE], g_W23[NLAT * KODE];

__device__ __forceinline__ uint32_t smem_u32(const void* p) {
    uint32_t a;
    asm("{ .reg .u64 t; cvta.to.shared.u64 t, %1; cvt.u32.u64 %0, t; }" : "=r"(a) : "l"(p));
    return a;
}
__device__ __forceinline__ void ldm_x4(uint32_t* r, uint32_t addr) {
    asm volatile("ldmatrix.sync.aligned.m8n8.x4.shared.b16 {%0,%1,%2,%3}, [%4];"
                 : "=r"(r[0]), "=r"(r[1]), "=r"(r[2]), "=r"(r[3]) : "r"(addr));
}
__device__ __forceinline__ void mma16816(float* d, const uint32_t* a, const uint32_t* b) {
    asm volatile("mma.sync.aligned.m16n8k16.row.col.f32.bf16.bf16.f32 "
                 "{%0,%1,%2,%3}, {%4,%5,%6,%7}, {%8,%9}, {%0,%1,%2,%3};"
                 : "+f"(d[0]), "+f"(d[1]), "+f"(d[2]), "+f"(d[3])
                 : "r"(a[0]), "r"(a[1]), "r"(a[2]), "r"(a[3]), "r"(b[0]), "r"(b[1]));
}
#define CP_ASYNC16(sa, gp) asm volatile("cp.async.cg.shared.global [%0], [%1], 16;" :: "r"(sa), "l"(gp) : "memory")
#define CP_COMMIT()        asm volatile("cp.async.commit_group;" ::: "memory")
#define CP_WAIT(n)         asm volatile("cp.async.wait_group %0;" :: "n"(n) : "memory")

__device__ __forceinline__ float sigm(float x) { return 1.f / (1.f + expf(-x)); }

__device__ __forceinline__ void split3_1(float v, bf16& o1, bf16& o2, bf16& o3) {
    o1 = __float2bfloat16(v);
    float r1 = v - __bfloat162float(o1);
    o2 = __float2bfloat16(r1);
    float r2 = r1 - __bfloat162float(o2);
    o3 = __float2bfloat16(r2);
}
__device__ __forceinline__ void split3_2(float v0, float v1,
                                         bf16* D1, bf16* D2, bf16* D3, size_t idx) {
    bf16 a1, a2, a3, b1, b2, b3;
    split3_1(v0, a1, a2, a3);
    split3_1(v1, b1, b2, b3);
    __nv_bfloat162 p1, p2, p3;
    p1.x = a1; p1.y = b1; p2.x = a2; p2.y = b2; p3.x = a3; p3.y = b3;
    *(__nv_bfloat162*)&D1[idx] = p1;
    *(__nv_bfloat162*)&D2[idx] = p2;
    *(__nv_bfloat162*)&D3[idx] = p3;
}

enum { EPI_GATES = 0, EPI_NEWH = 1, EPI_ODE1 = 2, EPI_EULER = 3, EPI_LOGITS = 4 };

#define STAGE_BYTES 30720            // 6 matrices x 64 rows x 80B stride
#define SMEM_BYTES  (2 * STAGE_BYTES)

// bf16x6 GEMM on mma.sync with two-level accumulation + cp.async 2-stage pipeline.
// C[m,n] = sum_k A[m,k]*B[n,k]. Block 128 thr = 4 warps (2x2), tile 64x64, K-chunk 32.
template <int EPI>
__global__ void __launch_bounds__(128) tgemm_k(
    const bf16* __restrict__ A0a, const bf16* __restrict__ A0b, const bf16* __restrict__ A0c, int lda0,
    const bf16* __restrict__ A1a, const bf16* __restrict__ A1b, const bf16* __restrict__ A1c, int lda1, int K0,
    const bf16* __restrict__ Ba, const bf16* __restrict__ Bb, const bf16* __restrict__ Bc, int ldb,
    int kseg, int nch,
    const float* __restrict__ bias0, const float* __restrict__ bias1,
    const float* __restrict__ ts, int t,
    const float* __restrict__ uptr, float* __restrict__ hptr,
    bf16* __restrict__ o1, bf16* __restrict__ o2, bf16* __restrict__ o3,
    float* __restrict__ outF)
{
    extern __shared__ __align__(16) char smx[];
    const uint32_t sb = smem_u32(smx);
    const uint32_t OA1 = 0, OA2 = 5120, OA3 = 10240, OB1 = 15360, OB2 = 20480, OB3 = 25600;

    const int tid = threadIdx.x, wid = tid >> 5, lane = tid & 31;
    const int m0 = blockIdx.x * 64, n0 = blockIdx.y * 64;
    const int kbase = blockIdx.z * kseg;
    const int mbL = (wid >> 1) * 32;
    const int nbL = (wid & 1) * 32;

    // per-thread staging slots: 2 slots = 2 rows x 1 vec8 each (thread tid -> rows, cols)
    const int srow0 = tid >> 2, sc8 = tid & 3;          // slot 0: rows 0..31
    const int srow1 = srow0 + 32;                        // slot 1: rows 32..63

    auto load_chunk = [&](int c, int st) {
        const int gk = kbase + c * 32;
        const bf16 *aa, *ab, *ac; int lA, ka;
        if (gk < K0) { aa = A0a; ab = A0b; ac = A0c; lA = lda0; ka = gk; }
        else         { aa = A1a; ab = A1b; ac = A1c; lA = lda1; ka = gk - K0; }
        const uint32_t base = sb + st * STAGE_BYTES;
#pragma unroll
        for (int i = 0; i < 2; i++) {
            int row = i ? srow1 : srow0;
            uint32_t so = (uint32_t)(row * 80 + sc8 * 16);
            size_t aoff = (size_t)(m0 + row) * lA + ka;
            size_t boff = (size_t)(n0 + row) * ldb + gk;
            CP_ASYNC16(base + OA1 + so, (const char*)(aa + aoff) + sc8 * 16);
            CP_ASYNC16(base + OA2 + so, (const char*)(ab + aoff) + sc8 * 16);
            CP_ASYNC16(base + OA3 + so, (const char*)(ac + aoff) + sc8 * 16);
            CP_ASYNC16(base + OB1 + so, (const char*)(Ba + boff) + sc8 * 16);
            CP_ASYNC16(base + OB2 + so, (const char*)(Bb + boff) + sc8 * 16);
            CP_ASYNC16(base + OB3 + so, (const char*)(Bc + boff) + sc8 * 16);
        }
        CP_COMMIT();
    };

    float acc[2][4][4];
#pragma unroll
    for (int i = 0; i < 2; i++)
#pragma unroll
        for (int j = 0; j < 4; j++)
#pragma unroll
            for (int q = 0; q < 4; q++) acc[i][j][q] = 0.f;

    const int lr  = lane & 15;
    const int lkb = (lane >> 4) * 16;

    load_chunk(0, 0);

    for (int c = 0; c < nch; c++) {
        const int st = c & 1;
        if (c + 1 < nch) { load_chunk(c + 1, st ^ 1); CP_WAIT(1); }
        else             { CP_WAIT(0); }
        __syncthreads();
        const uint32_t base = sb + st * STAGE_BYTES;
        // ---- 2 k16 steps on stage st ----
#pragma unroll
        for (int kh = 0; kh < 2; kh++) {
            uint32_t a1[2][4], a2[2][4], a3[2][4], b1[2][4], b2[2][4], b3[2][4];
#pragma unroll
            for (int tm = 0; tm < 2; tm++) {
                uint32_t ro = (uint32_t)((mbL + tm * 16 + lr) * 80 + kh * 32 + lkb);
                ldm_x4(a1[tm], base + OA1 + ro);
                ldm_x4(a2[tm], base + OA2 + ro);
                ldm_x4(a3[tm], base + OA3 + ro);
            }
#pragma unroll
            for (int p = 0; p < 2; p++) {
                uint32_t ro = (uint32_t)((nbL + p * 16 + lr) * 80 + kh * 32 + lkb);
                ldm_x4(b1[p], base + OB1 + ro);
                ldm_x4(b2[p], base + OB2 + ro);
                ldm_x4(b3[p], base + OB3 + ro);
            }
#pragma unroll
            for (int tm = 0; tm < 2; tm++)
#pragma unroll
                for (int tn = 0; tn < 4; tn++) {
                    int p = tn >> 1, q = tn & 1;
                    uint32_t B1f[2] = { b1[p][q], b1[p][q + 2] };
                    uint32_t B2f[2] = { b2[p][q], b2[p][q + 2] };
                    uint32_t B3f[2] = { b3[p][q], b3[p][q + 2] };
                    // fresh fragment: short RZ chain inside the tensor core
                    float m4[4] = {0.f, 0.f, 0.f, 0.f};
                    mma16816(m4, a3[tm], B1f);
                    mma16816(m4, a1[tm], B3f);
                    mma16816(m4, a2[tm], B2f);
                    mma16816(m4, a2[tm], B1f);
                    mma16816(m4, a1[tm], B2f);
                    mma16816(m4, a1[tm], B1f);
                    // promote to master accumulator with RN adds
                    acc[tm][tn][0] += m4[0];
                    acc[tm][tn][1] += m4[1];
                    acc[tm][tn][2] += m4[2];
                    acc[tm][tn][3] += m4[3];
                }
        }
        __syncthreads();
    }

    // ---- epilogue: c0,c1 -> row lane>>2, cols 2*(lane&3)+{0,1}; c2,c3 -> row+8
    const int er = lane >> 2, ec = (lane & 3) * 2;
#pragma unroll
    for (int tm = 0; tm < 2; tm++)
#pragma unroll
        for (int tn = 0; tn < 4; tn++)
#pragma unroll
            for (int half = 0; half < 2; half++) {
                int row = m0 + mbL + tm * 16 + er + half * 8;
                int col = n0 + nbL + tn * 8 + ec;
                float v0 = acc[tm][tn][half * 2 + 0];
                float v1 = acc[tm][tn][half * 2 + 1];
                if (EPI == EPI_GATES) {
                    if (n0 < NLAT) {                    // u half
                        float2 o;
                        o.x = sigm(v0 + bias0[col]);
                        o.y = sigm(v1 + bias0[col + 1]);
                        *(float2*)&outF[(size_t)row * NLAT + col] = o;
                    } else {                            // r half -> hr = h * sigmoid
                        int cc = col - NLAT;
                        float2 hv = *(const float2*)&hptr[(size_t)row * NLAT + cc];
                        float r0 = hv.x * sigm(v0 + bias1[cc]);
                        float r1 = hv.y * sigm(v1 + bias1[cc + 1]);
                        split3_2(r0, r1, o1, o2, o3, (size_t)row * NLAT + cc);
                    }
                } else if (EPI == EPI_NEWH) {
                    float2 uu = *(const float2*)&uptr[(size_t)row * NLAT + col];
                    float2 ho = *(const float2*)&hptr[(size_t)row * NLAT + col];
                    float w0 = (1.f - uu.x) * (v0 + bias0[col])     + uu.x * ho.x;
                    float w1 = (1.f - uu.y) * (v1 + bias0[col + 1]) + uu.y * ho.y;
                    *(float2*)&hptr[(size_t)row * NLAT + col] = make_float2(w0, w1);
                    split3_2(w0, w1, o1, o2, o3, (size_t)row * NLAT + col);
                } else if (EPI == EPI_ODE1) {
                    *(float2*)&outF[(size_t)blockIdx.z * (NTRAJ * KODE)
                                    + (size_t)row * KODE + col] = make_float2(v0, v1);
                } else if (EPI == EPI_EULER) {
                    float sub = 0.5f * (ts[t + 1] - ts[t]);
                    float2 ho = *(const float2*)&hptr[(size_t)row * NLAT + col];
                    float w0 = ho.x + sub * (v0 + bias0[col]);
                    float w1 = ho.y + sub * (v1 + bias0[col + 1]);
                    *(float2*)&hptr[(size_t)row * NLAT + col] = make_float2(w0, w1);
                    split3_2(w0, w1, o1, o2, o3, (size_t)row * NLAT + col);
                } else { // EPI_LOGITS
                    *(float2*)&outF[(size_t)blockIdx.z * (NTRAJ * NCLUS)
                                    + (size_t)row * NCLUS + col] = make_float2(v0, v1);
                }
            }
}

// L0: split data (blocks 0..65535) + zero h (blocks 65536..67583)
__global__ void prep0_k(const float* __restrict__ d,
                        bf16* __restrict__ x1, bf16* __restrict__ x2, bf16* __restrict__ x3,
                        float* __restrict__ h,
                        bf16* __restrict__ h1, bf16* __restrict__ h2, bf16* __restrict__ h3)
{
    if (blockIdx.x < 65536) {
        size_t i = (size_t)blockIdx.x * 256 + threadIdx.x;
        bf16 a, b, c;
        split3_1(d[i], a, b, c);
        x1[i] = a; x2[i] = b; x3[i] = c;
    } else {
        int i = (blockIdx.x - 65536) * 256 + threadIdx.x;
        h[i] = 0.f;
        bf16 z = __float2bfloat16(0.f);
        h1[i] = z; h2[i] = z; h3[i] = z;
    }
}

// transpose + 3-split: out[n][k] = (k<Ksrc && n<Nsrc) ? src[k][n] : 0
__device__ __forceinline__ void tsplit_body(const float* src, int Ksrc, int Nsrc,
                                            bf16* d1, bf16* d2, bf16* d3, int Kout)
{
    __shared__ float tile[32][33];
    const int kb = blockIdx.x * 32, nb = blockIdx.y * 32;
    const int tx = threadIdx.x, ty = threadIdx.y;
    int k = kb + ty, n = nb + tx;
    tile[ty][tx] = (k < Ksrc && n < Nsrc) ? src[(size_t)k * Nsrc + n] : 0.f;
    __syncthreads();
    int on = nb + ty, ok = kb + tx;
    float v = tile[tx][ty];
    bf16 a, b, c;
    split3_1(v, a, b, c);
    d1[(size_t)on * Kout + ok] = a;
    d2[(size_t)on * Kout + ok] = b;
    d3[(size_t)on * Kout + ok] = c;
}

// L1: W_u / W_r / W_n batched on gridDim.z
__global__ void tsplit_gn_k(const float* __restrict__ Wu, const float* __restrict__ Wr,
                            const float* __restrict__ Wn,
                            bf16* __restrict__ Wg1, bf16* __restrict__ Wg2, bf16* __restrict__ Wg3,
                            bf16* __restrict__ Wn1, bf16* __restrict__ Wn2, bf16* __restrict__ Wn3)
{
    const size_t off = (size_t)NLAT * DCAT;
    if (blockIdx.z == 0)      tsplit_body(Wu, DCAT, NLAT, Wg1, Wg2, Wg3, DCAT);
    else if (blockIdx.z == 1) tsplit_body(Wr, DCAT, NLAT, Wg1 + off, Wg2 + off, Wg3 + off, DCAT);
    else                      tsplit_body(Wn, DCAT, NLAT, Wn1, Wn2, Wn3, DCAT);
}

__global__ void tsplit_k(const float* __restrict__ src, int Ksrc, int Nsrc,
                         bf16* __restrict__ d1, bf16* __restrict__ d2,
                         bf16* __restrict__ d3, int Kout)
{
    tsplit_body(src, Ksrc, Nsrc, d1, d2, d3, Kout);
}

__global__ void tanhsplit_k(const float* __restrict__ t1p, const float* __restrict__ b1,
                            bf16* __restrict__ t1, bf16* __restrict__ t2, bf16* __restrict__ t3)
{
    int i = blockIdx.x * 256 + threadIdx.x;   // 65536 total
    int c = i & (KODE - 1);
    float s = 0.f;
    if (c < NUNITS) {
        s = b1[c];
#pragma unroll
        for (int z = 0; z < 4; z++) s += t1p[z * (NTRAJ * KODE) + i];
        s = tanhf(s);
    }
    bf16 a, b, d;
    split3_1(s, a, b, d);
    t1[i] = a; t2[i] = b; t3[i] = d;
}

__global__ void __launch_bounds__(256) softmax_states_k(
    const float* __restrict__ lp, const float* __restrict__ be,
    const float* __restrict__ h,
    float* __restrict__ prob_out, float* __restrict__ state_out)
{
    const int row = blockIdx.x;
    const int tid = threadIdx.x;
    __shared__ float smax[8], ssum[8];

    float v = be[tid] + lp[(size_t)row * NCLUS + tid]
                      + lp[(size_t)NTRAJ * NCLUS + (size_t)row * NCLUS + tid];
    float m = v;
#pragma unroll
    for (int o = 16; o > 0; o >>= 1) m = fmaxf(m, __shfl_xor_sync(0xffffffffu, m, o));
    if ((tid & 31) == 0) smax[tid >> 5] = m;
    __syncthreads();
    float mx = smax[0];
#pragma unroll
    for (int w = 1; w < 8; w++) mx = fmaxf(mx, smax[w]);

    float e = expf(v - mx);
    float s = e;
#pragma unroll
    for (int o = 16; o > 0; o >>= 1) s += __shfl_xor_sync(0xffffffffu, s, o);
    if ((tid & 31) == 0) ssum[tid >> 5] = s;
    __syncthreads();
    float tot = 0.f;
#pragma unroll
    for (int w = 0; w < 8; w++) tot += ssum[w];

    prob_out[(size_t)row * NCLUS + tid] = e / tot;
#pragma unroll
    for (int i = 0; i < 4; i++)
        state_out[(size_t)row * NLAT + i * 256 + tid] = h[(size_t)row * NLAT + i * 256 + tid];
}

extern "C" void kernel_launch(void* const* d_in, const int* in_sizes, int n_in,
                              void* d_out, int out_size)
{
    const float* data = (const float*)d_in[0];
    const float* ts   = (const float*)d_in[1];
    const float* W_u  = (const float*)d_in[2];
    const float* b_u  = (const float*)d_in[3];
    const float* W_r  = (const float*)d_in[4];
    const float* b_r  = (const float*)d_in[5];
    const float* W_n  = (const float*)d_in[6];
    const float* b_n  = (const float*)d_in[7];
    const float* W1   = (const float*)d_in[8];
    const float* b1   = (const float*)d_in[9];
    const float* W2   = (const float*)d_in[10];
    const float* b2   = (const float*)d_in[11];
    const float* We   = (const float*)d_in[12];
    const float* be   = (const float*)d_in[13];
    float* out = (float*)d_out;

    cudaFuncSetAttribute(tgemm_k<EPI_GATES>,  cudaFuncAttributeMaxDynamicSharedMemorySize, SMEM_BYTES);
    cudaFuncSetAttribute(tgemm_k<EPI_NEWH>,   cudaFuncAttributeMaxDynamicSharedMemorySize, SMEM_BYTES);
    cudaFuncSetAttribute(tgemm_k<EPI_ODE1>,   cudaFuncAttributeMaxDynamicSharedMemorySize, SMEM_BYTES);
    cudaFuncSetAttribute(tgemm_k<EPI_EULER>,  cudaFuncAttributeMaxDynamicSharedMemorySize, SMEM_BYTES);
    cudaFuncSetAttribute(tgemm_k<EPI_LOGITS>, cudaFuncAttributeMaxDynamicSharedMemorySize, SMEM_BYTES);

    float *h, *u, *t1p, *lp;
    bf16 *h1, *h2, *h3, *hr1, *hr2, *hr3, *t11, *t12, *t13, *X1, *X2, *X3;
    bf16 *Wg1, *Wg2, *Wg3, *Wn1, *Wn2, *Wn3, *We1, *We2, *We3;
    bf16 *W11, *W12, *W13, *W21, *W22, *W23;
    cudaGetSymbolAddress((void**)&h, g_h);     cudaGetSymbolAddress((void**)&u, g_u);
    cudaGetSymbolAddress((void**)&t1p, g_t1p); cudaGetSymbolAddress((void**)&lp, g_lp);
    cudaGetSymbolAddress((void**)&h1, g_h1);   cudaGetSymbolAddress((void**)&h2, g_h2);
    cudaGetSymbolAddress((void**)&h3, g_h3);
    cudaGetSymbolAddress((void**)&hr1, g_hr1); cudaGetSymbolAddress((void**)&hr2, g_hr2);
    cudaGetSymbolAddress((void**)&hr3, g_hr3);
    cudaGetSymbolAddress((void**)&t11, g_t11); cudaGetSymbolAddress((void**)&t12, g_t12);
    cudaGetSymbolAddress((void**)&t13, g_t13);
    cudaGetSymbolAddress((void**)&X1, g_X1);   cudaGetSymbolAddress((void**)&X2, g_X2);
    cudaGetSymbolAddress((void**)&X3, g_X3);
    cudaGetSymbolAddress((void**)&Wg1, g_Wg1); cudaGetSymbolAddress((void**)&Wg2, g_Wg2);
    cudaGetSymbolAddress((void**)&Wg3, g_Wg3);
    cudaGetSymbolAddress((void**)&Wn1, g_Wn1); cudaGetSymbolAddress((void**)&Wn2, g_Wn2);
    cudaGetSymbolAddress((void**)&Wn3, g_Wn3);
    cudaGetSymbolAddress((void**)&We1, g_We1); cudaGetSymbolAddress((void**)&We2, g_We2);
    cudaGetSymbolAddress((void**)&We3, g_We3);
    cudaGetSymbolAddress((void**)&W11, g_W11); cudaGetSymbolAddress((void**)&W12, g_W12);
    cudaGetSymbolAddress((void**)&W13, g_W13);
    cudaGetSymbolAddress((void**)&W21, g_W21); cudaGetSymbolAddress((void**)&W22, g_W22);
    cudaGetSymbolAddress((void**)&W23, g_W23);

    // -------- prep: exactly 5 launches so ncu (-s 5) profiles the gates GEMM --------
    prep0_k<<<65536 + 2048, 256>>>(data, X1, X2, X3, h, h1, h2, h3);
    tsplit_gn_k<<<dim3(DCAT/32, NLAT/32, 3), dim3(32,32)>>>(W_u, W_r, W_n,
        Wg1, Wg2, Wg3, Wn1, Wn2, Wn3);
    tsplit_k<<<dim3(NLAT/32, NCLUS/32), dim3(32,32)>>>(We, NLAT, NCLUS, We1, We2, We3, NLAT);
    tsplit_k<<<dim3(NLAT/32, KODE/32),  dim3(32,32)>>>(W1, NLAT, NUNITS, W11, W12, W13, NLAT);
    tsplit_k<<<dim3(KODE/32, NLAT/32),  dim3(32,32)>>>(W2, NUNITS, NLAT, W21, W22, W23, KODE);

    float* probs  = out;
    float* states = out + (size_t)NSTEP * NTRAJ * NCLUS;
    const int BIGK = 1 << 30;

    for (int t = 0; t < NSTEP; t++) {
        // u,r gates: [h|x] @ [W_u|W_r]^T; emits u and split3(h*r)
        tgemm_k<EPI_GATES><<<dim3(8, 32, 1), 128, SMEM_BYTES>>>(
            h1, h2, h3, NLAT,
            X1 + (size_t)t*NIN, X2 + (size_t)t*NIN, X3 + (size_t)t*NIN, NTP*NIN, NLAT,
            Wg1, Wg2, Wg3, DCAT, DCAT, 48,
            b_u, b_r, nullptr, 0, nullptr, h, hr1, hr2, hr3, u);
        // n + GRU blend: h = (1-u)*([h*r|x]@W_n + b_n) + u*h; emits split3(h)
        tgemm_k<EPI_NEWH><<<dim3(8, 16, 1), 128, SMEM_BYTES>>>(
            hr1, hr2, hr3, NLAT,
            X1 + (size_t)t*NIN, X2 + (size_t)t*NIN, X3 + (size_t)t*NIN, NTP*NIN, NLAT,
            Wn1, Wn2, Wn3, DCAT, DCAT, 48,
            b_n, nullptr, nullptr, 0, u, h, h1, h2, h3, nullptr);
        // 2 Euler steps: h += sub * (tanh(h@W1+b1) @ W2 + b2)
        for (int e = 0; e < 2; e++) {
            tgemm_k<EPI_ODE1><<<dim3(8, 2, 4), 128, SMEM_BYTES>>>(
                h1, h2, h3, NLAT, nullptr, nullptr, nullptr, 0, BIGK,
                W11, W12, W13, NLAT, 256, 8,
                nullptr, nullptr, nullptr, 0, nullptr, nullptr,
                nullptr, nullptr, nullptr, t1p);
            tanhsplit_k<<<256, 256>>>(t1p, b1, t11, t12, t13);
            tgemm_k<EPI_EULER><<<dim3(8, 16, 1), 128, SMEM_BYTES>>>(
                t11, t12, t13, KODE, nullptr, nullptr, nullptr, 0, BIGK,
                W21, W22, W23, KODE, KODE, 4,
                b2, nullptr, ts, t, nullptr, h, h1, h2, h3, nullptr);
        }
        // emission logits (K split x2), then softmax + state copy
        tgemm_k<EPI_LOGITS><<<dim3(8, 4, 2), 128, SMEM_BYTES>>>(
            h1, h2, h3, NLAT, nullptr, nullptr, nullptr, 0, BIGK,
            We1, We2, We3, NLAT, 512, 16,
            nullptr, nullptr, nullptr, 0, nullptr, nullptr,
            nullptr, nullptr, nullptr, lp);
        softmax_states_k<<<NTRAJ, 256>>>(lp, be, h,
            probs  + (size_t)t * NTRAJ * NCLUS,
            states + (size_t)t * NTRAJ * NLAT);
    }
}